// round 6
// baseline (speedup 1.0000x reference)
#include <cuda_runtime.h>
#include <cuda_fp16.h>
#include <cstdint>
#include <cstddef>

#define BB    8192
#define DIN   1024
#define CCAP  12
#define DOUT  1024
#define NTOT  12288
#define AREP  8

#define SX 5300.0f
#define SW 165000.0f

// ---------------- device scratch (static; no allocation) ----------------
__device__ int8_t g_xh8[(size_t)BB * DIN];
__device__ int8_t g_xl8[(size_t)BB * DIN];
__device__ int8_t g_wh8[(size_t)NTOT * DIN];
__device__ int8_t g_wl8[(size_t)NTOT * DIN];
__device__ float  g_u [(size_t)BB * NTOT];     // 384 MB
__device__ float  g_ent[BB];

// ---------------- PTX helpers ----------------
__device__ __forceinline__ uint32_t smem_u32(const void* p) {
    uint32_t a;
    asm("{ .reg .u64 t; cvta.to.shared.u64 t, %1; cvt.u32.u64 %0, t; }" : "=r"(a) : "l"(p));
    return a;
}
__device__ __forceinline__ void cp_async16(uint32_t sdst, const void* gsrc) {
    asm volatile("cp.async.cg.shared.global [%0], [%1], 16;" :: "r"(sdst), "l"(gsrc) : "memory");
}
#define CP_COMMIT() asm volatile("cp.async.commit_group;" ::: "memory")
#define CP_WAIT(N)  asm volatile("cp.async.wait_group %0;" :: "n"(N) : "memory")

__device__ __forceinline__ void ldsm_x4(uint32_t addr, uint32_t& r0, uint32_t& r1,
                                        uint32_t& r2, uint32_t& r3) {
    asm volatile("ldmatrix.sync.aligned.m8n8.x4.shared.b16 {%0,%1,%2,%3}, [%4];"
                 : "=r"(r0), "=r"(r1), "=r"(r2), "=r"(r3) : "r"(addr));
}
__device__ __forceinline__ void mma_s8(int* c, const uint32_t* a, const uint32_t* b) {
    asm volatile(
        "mma.sync.aligned.m16n8k32.row.col.s32.s8.s8.s32 "
        "{%0,%1,%2,%3},{%4,%5,%6,%7},{%8,%9},{%0,%1,%2,%3};"
        : "+r"(c[0]), "+r"(c[1]), "+r"(c[2]), "+r"(c[3])
        : "r"(a[0]), "r"(a[1]), "r"(a[2]), "r"(a[3]), "r"(b[0]), "r"(b[1]));
}

// ---------------- K0: fp32 -> int8 (hi, lo) quantization ----------------
__global__ void quant_kernel(const float* __restrict__ src,
                             int8_t* __restrict__ hi, int8_t* __restrict__ lo, float S) {
    size_t i = (size_t)blockIdx.x * blockDim.x + threadIdx.x;
    float4 f = ((const float4*)src)[i];
    float v[4] = {f.x, f.y, f.z, f.w};
    char h[4], l[4];
#pragma unroll
    for (int j = 0; j < 4; j++) {
        int q = __float2int_rn(fminf(fmaxf(v[j] * S, -32640.f), 32639.f));
        int qh = (q + 128) >> 8;           // qh in [-127,127]
        int ql = q - (qh << 8);            // ql in [-128,127], exact
        h[j] = (char)qh; l[j] = (char)ql;
    }
    ((char4*)hi)[i] = make_char4(h[0], h[1], h[2], h[3]);
    ((char4*)lo)[i] = make_char4(l[0], l[1], l[2], l[3]);
}

// ---------------- K1: exact int16-via-int8 GEMM  u = x @ W^T + bias ----------
#define BM 128
#define BN 128
#define BK 32
#define STAGES 4
#define NSTG (DIN / BK)            // 32
#define PITCH 48                   // 32 B data + 16 B pad
#define T_BYTES (128 * PITCH)      // 6144
#define STG_BYTES (4 * T_BYTES)    // 24576: AH | AL | BH | BL
#define SMEM_TOTAL (STAGES * STG_BYTES)   // 98304

__global__ void __launch_bounds__(256, 1)
gemm_kernel(const float* __restrict__ bias) {
    extern __shared__ __align__(128) char smem[];
    uint32_t sb = smem_u32(smem);
    const int tid  = threadIdx.x;
    const int wid  = tid >> 5;
    const int lane = tid & 31;

    const int NT = NTOT / BN;      // 96
    const int GM = 16;
    int id = blockIdx.x;
    int group = id / (GM * NT), rem = id % (GM * NT);
    const int m0 = (group * GM + (rem % GM)) * BM;
    const int n0 = (rem / GM) * BN;

    const int wr = wid & 1;        // 2 m-warps
    const int wc = wid >> 1;       // 4 n-warps; warp tile 64 x 32

    const int r  = tid >> 1, ch = tid & 1;
    const uint32_t soff = (uint32_t)(r * PITCH + ch * 16);
    const size_t a_g = (size_t)(m0 + r) * DIN + ch * 16;
    const size_t b_g = (size_t)(n0 + r) * DIN + ch * 16;

    auto load_stage = [&](int ks) {
        uint32_t st = sb + (ks & 3) * STG_BYTES;
        int koff = ks * BK;
        cp_async16(st + soff,               g_xh8 + a_g + koff);
        cp_async16(st + T_BYTES + soff,     g_xl8 + a_g + koff);
        cp_async16(st + 2 * T_BYTES + soff, g_wh8 + b_g + koff);
        cp_async16(st + 3 * T_BYTES + soff, g_wl8 + b_g + koff);
        CP_COMMIT();
    };

    int c1[4][4][4], c2[4][4][4], c3[4][4][4];
#pragma unroll
    for (int i = 0; i < 4; i++)
#pragma unroll
        for (int j = 0; j < 4; j++)
#pragma unroll
            for (int k = 0; k < 4; k++) { c1[i][j][k] = 0; c2[i][j][k] = 0; c3[i][j][k] = 0; }

    load_stage(0); load_stage(1); load_stage(2);

    const uint32_t a_lane = (uint32_t)(((lane & 7) + ((lane >> 3) & 1) * 8) * PITCH
                                       + (lane >> 4) * 16);
    const uint32_t b_lane = (uint32_t)(((lane & 7) + (lane >> 4) * 8) * PITCH
                                       + ((lane >> 3) & 1) * 16);

    for (int ks = 0; ks < NSTG; ks++) {
        if (ks < NSTG - 2)       { CP_WAIT(2); }
        else if (ks == NSTG - 2) { CP_WAIT(1); }
        else                     { CP_WAIT(0); }
        __syncthreads();
        if (ks + 3 < NSTG) load_stage(ks + 3);

        uint32_t st = sb + (ks & 3) * STG_BYTES;
        uint32_t ah_base = st + wr * 64 * PITCH + a_lane;
        uint32_t al_base = ah_base + T_BYTES;
        uint32_t bh_base = st + 2 * T_BYTES + wc * 32 * PITCH + b_lane;
        uint32_t bl_base = bh_base + T_BYTES;

        uint32_t ah[4][4], al[4][4];
#pragma unroll
        for (int mt = 0; mt < 4; mt++) {
            ldsm_x4(ah_base + mt * 16 * PITCH, ah[mt][0], ah[mt][1], ah[mt][2], ah[mt][3]);
            ldsm_x4(al_base + mt * 16 * PITCH, al[mt][0], al[mt][1], al[mt][2], al[mt][3]);
        }
#pragma unroll
        for (int g = 0; g < 2; g++) {
            uint32_t bh[4], bl[4];
            ldsm_x4(bh_base + g * 16 * PITCH, bh[0], bh[1], bh[2], bh[3]);
            ldsm_x4(bl_base + g * 16 * PITCH, bl[0], bl[1], bl[2], bl[3]);
            // sweep 1: hi*hi -> c1, hi*lo -> c2
#pragma unroll
            for (int mt = 0; mt < 4; mt++)
#pragma unroll
                for (int p = 0; p < 2; p++) {
                    int nt = g * 2 + p;
                    mma_s8(c1[mt][nt], ah[mt], bh + 2 * p);
                    mma_s8(c2[mt][nt], ah[mt], bl + 2 * p);
                }
            // sweep 2: lo*hi -> c2, lo*lo -> c3 (c2 re-touch spaced by 8 mmas)
#pragma unroll
            for (int mt = 0; mt < 4; mt++)
#pragma unroll
                for (int p = 0; p < 2; p++) {
                    int nt = g * 2 + p;
                    mma_s8(c2[mt][nt], al[mt], bh + 2 * p);
                    mma_s8(c3[mt][nt], al[mt], bl + 2 * p);
                }
        }
        __syncthreads();
    }

    // epilogue: u = (c1*65536 + c2*256 + c3) / (SX*SW) + bias   (exact integer combine in fp32)
    const float fin = 1.f / (SX * SW);
    const int rbase = m0 + wr * 64 + (lane >> 2);
    const int cbase = n0 + wc * 32 + (lane & 3) * 2;
#pragma unroll
    for (int nt = 0; nt < 4; nt++) {
        int col = cbase + nt * 8;
        float2 bv = *(const float2*)(bias + col);
#pragma unroll
        for (int mt = 0; mt < 4; mt++) {
            int r0 = rbase + mt * 16;
            float t0 = fmaf((float)c1[mt][nt][0], 65536.f, fmaf((float)c2[mt][nt][0], 256.f, (float)c3[mt][nt][0]));
            float t1 = fmaf((float)c1[mt][nt][1], 65536.f, fmaf((float)c2[mt][nt][1], 256.f, (float)c3[mt][nt][1]));
            float t2 = fmaf((float)c1[mt][nt][2], 65536.f, fmaf((float)c2[mt][nt][2], 256.f, (float)c3[mt][nt][2]));
            float t3 = fmaf((float)c1[mt][nt][3], 65536.f, fmaf((float)c2[mt][nt][3], 256.f, (float)c3[mt][nt][3]));
            float* p0 = g_u + (size_t)r0 * NTOT + col;
            float* p1 = g_u + (size_t)(r0 + 8) * NTOT + col;
            *(float2*)p0 = make_float2(fmaf(t0, fin, bv.x), fmaf(t1, fin, bv.y));
            *(float2*)p1 = make_float2(fmaf(t2, fin, bv.x), fmaf(t3, fin, bv.y));
        }
    }
}

// ---------------- K2: per-row routing + entropy ----------------
__device__ __forceinline__ float bsum(float v, float* s8, int wid, int lid) {
#pragma unroll
    for (int o = 16; o > 0; o >>= 1) v += __shfl_down_sync(0xffffffffu, v, o);
    __syncthreads();
    if (lid == 0) s8[wid] = v;
    __syncthreads();
    float r = 0.f;
#pragma unroll
    for (int w = 0; w < 8; w++) r += s8[w];
    return r;
}
__device__ __forceinline__ float bmax(float v, float* s8, int wid, int lid) {
#pragma unroll
    for (int o = 16; o > 0; o >>= 1) v = fmaxf(v, __shfl_down_sync(0xffffffffu, v, o));
    __syncthreads();
    if (lid == 0) s8[wid] = v;
    __syncthreads();
    float r = s8[0];
#pragma unroll
    for (int w = 1; w < 8; w++) r = fmaxf(r, s8[w]);
    return r;
}

__global__ void __launch_bounds__(256) routing_kernel(float* __restrict__ out) {
    __shared__ float s_red[8 * CCAP];
    __shared__ float s_s8[8];
    int b = blockIdx.x, tid = threadIdx.x;
    int wid = tid >> 5, lid = tid & 31;

    const float* up = g_u + (size_t)b * NTOT + tid * 4;
    float u[CCAP][4];
#pragma unroll
    for (int cc = 0; cc < CCAP; cc++) {
        float4 f = *(const float4*)(up + cc * DOUT);
        u[cc][0] = f.x; u[cc][1] = f.y; u[cc][2] = f.z; u[cc][3] = f.w;
    }

    float blog[CCAP];
#pragma unroll
    for (int cc = 0; cc < CCAP; cc++) blog[cc] = 0.f;

    float s[4] = {0.f, 0.f, 0.f, 0.f}, scale = 0.f;
#pragma unroll 1
    for (int it = 0; it < 3; it++) {
        float mx = blog[0];
#pragma unroll
        for (int cc = 1; cc < CCAP; cc++) mx = fmaxf(mx, blog[cc]);
        float cw[CCAP], csum = 0.f;
#pragma unroll
        for (int cc = 0; cc < CCAP; cc++) { cw[cc] = expf(blog[cc] - mx); csum += cw[cc]; }
        float inv = 1.f / csum;
#pragma unroll
        for (int j = 0; j < 4; j++) {
            float a = 0.f;
#pragma unroll
            for (int cc = 0; cc < CCAP; cc++) a += cw[cc] * u[cc][j];
            s[j] = a * inv;
        }
        float n2 = bsum(s[0]*s[0] + s[1]*s[1] + s[2]*s[2] + s[3]*s[3], s_s8, wid, lid);
        float nrm = sqrtf(n2);
        scale = n2 / ((1.f + n2) * (nrm + 1e-8f));
        if (it < 2) {
            float dp[CCAP];
#pragma unroll
            for (int cc = 0; cc < CCAP; cc++) {
                float a = u[cc][0]*s[0] + u[cc][1]*s[1] + u[cc][2]*s[2] + u[cc][3]*s[3];
#pragma unroll
                for (int o = 16; o > 0; o >>= 1) a += __shfl_down_sync(0xffffffffu, a, o);
                dp[cc] = a;
            }
            __syncthreads();
            if (lid == 0)
#pragma unroll
                for (int cc = 0; cc < CCAP; cc++) s_red[wid * CCAP + cc] = dp[cc];
            __syncthreads();
#pragma unroll
            for (int cc = 0; cc < CCAP; cc++) {
                float d = 0.f;
#pragma unroll
                for (int w = 0; w < 8; w++) d += s_red[w * CCAP + cc];
                blog[cc] += scale * d;
            }
        }
    }

    float4 v4 = make_float4(scale * s[0], scale * s[1], scale * s[2], scale * s[3]);
    size_t obase = ((size_t)b * AREP) * DOUT + tid * 4;
#pragma unroll
    for (int a = 0; a < AREP; a++) *(float4*)(out + obase + (size_t)a * DOUT) = v4;

    float smx = bmax(fmaxf(fmaxf(s[0], s[1]), fmaxf(s[2], s[3])), s_s8, wid, lid);
    float e[4], zp = 0.f;
#pragma unroll
    for (int j = 0; j < 4; j++) { e[j] = expf(s[j] - smx); zp += e[j]; }
    float Z = bsum(zp, s_s8, wid, lid) + 1e-10f;
    float ep = 0.f;
#pragma unroll
    for (int j = 0; j < 4; j++) { float p = e[j] / Z; ep -= p * logf(p + 1e-10f); }
    float ent = bsum(ep, s_s8, wid, lid);
    if (tid == 0) g_ent[b] = fminf(fmaxf(ent, 0.f), 10.f);
}

// ---------------- K3: entropy loss scalar ----------------
__global__ void loss_kernel(float* __restrict__ dst) {
    __shared__ float s8[8];
    int tid = threadIdx.x, wid = tid >> 5, lid = tid & 31;
    float a = 0.f;
    for (int i = tid; i < BB; i += 256) a += g_ent[i];
#pragma unroll
    for (int o = 16; o > 0; o >>= 1) a += __shfl_down_sync(0xffffffffu, a, o);
    if (lid == 0) s8[wid] = a;
    __syncthreads();
    if (tid == 0) {
        float t = 0.f;
#pragma unroll
        for (int w = 0; w < 8; w++) t += s8[w];
        float mean = t / (float)BB;
        dst[0] = -(1.f / (1.f + expf(-mean))) * 0.4f;
    }
}

// ---------------- launch ----------------
extern "C" void kernel_launch(void* const* d_in, const int* in_sizes, int n_in,
                              void* d_out, int out_size) {
    const float* x    = (const float*)d_in[0];
    const float* W    = (const float*)d_in[1];
    const float* bias = (const float*)d_in[2];
    float* out = (float*)d_out;

    cudaFuncSetAttribute(gemm_kernel, cudaFuncAttributeMaxDynamicSharedMemorySize, SMEM_TOTAL);

    int8_t *xh, *xl, *wh, *wl;
    cudaGetSymbolAddress((void**)&xh, g_xh8);
    cudaGetSymbolAddress((void**)&xl, g_xl8);
    cudaGetSymbolAddress((void**)&wh, g_wh8);
    cudaGetSymbolAddress((void**)&wl, g_wl8);

    quant_kernel<<<(BB * DIN / 4) / 256, 256>>>(x, xh, xl, SX);
    quant_kernel<<<((size_t)NTOT * DIN / 4) / 256, 256>>>(W, wh, wl, SW);
    gemm_kernel<<<(BB / BM) * (NTOT / BN), 256, SMEM_TOTAL>>>(bias);
    routing_kernel<<<BB, 256>>>(out);
    loss_kernel<<<1, 256>>>(out + (size_t)out_size - 1);
}

// round 8
// speedup vs baseline: 1.0669x; 1.0669x over previous
#include <cuda_runtime.h>
#include <cuda_fp16.h>
#include <cstdint>
#include <cstddef>

#define BB    8192
#define DIN   1024
#define CCAP  12
#define DOUT  1024
#define NTOT  12288
#define AREP  8

#define SX 5300.0f
#define SW 165000.0f

// ---------------- device scratch (static; no allocation) ----------------
__device__ int8_t g_xh8[(size_t)BB * DIN];
__device__ int8_t g_xl8[(size_t)BB * DIN];
__device__ int8_t g_wh8[(size_t)NTOT * DIN];
__device__ int8_t g_wl8[(size_t)NTOT * DIN];
__device__ float  g_u [(size_t)BB * NTOT];     // 384 MB
__device__ float  g_ent[BB];

// ---------------- PTX helpers ----------------
__device__ __forceinline__ uint32_t smem_u32(const void* p) {
    uint32_t a;
    asm("{ .reg .u64 t; cvta.to.shared.u64 t, %1; cvt.u32.u64 %0, t; }" : "=r"(a) : "l"(p));
    return a;
}
__device__ __forceinline__ void cp_async16(uint32_t sdst, const void* gsrc) {
    asm volatile("cp.async.cg.shared.global [%0], [%1], 16;" :: "r"(sdst), "l"(gsrc) : "memory");
}
#define CP_COMMIT() asm volatile("cp.async.commit_group;" ::: "memory")
#define CP_WAIT(N)  asm volatile("cp.async.wait_group %0;" :: "n"(N) : "memory")

__device__ __forceinline__ void ldsm_x4(uint32_t addr, uint32_t& r0, uint32_t& r1,
                                        uint32_t& r2, uint32_t& r3) {
    asm volatile("ldmatrix.sync.aligned.m8n8.x4.shared.b16 {%0,%1,%2,%3}, [%4];"
                 : "=r"(r0), "=r"(r1), "=r"(r2), "=r"(r3) : "r"(addr));
}
__device__ __forceinline__ void mma_s8(int* c, const uint32_t* a, const uint32_t* b) {
    asm volatile(
        "mma.sync.aligned.m16n8k32.row.col.s32.s8.s8.s32 "
        "{%0,%1,%2,%3},{%4,%5,%6,%7},{%8,%9},{%0,%1,%2,%3};"
        : "+r"(c[0]), "+r"(c[1]), "+r"(c[2]), "+r"(c[3])
        : "r"(a[0]), "r"(a[1]), "r"(a[2]), "r"(a[3]), "r"(b[0]), "r"(b[1]));
}

// ---------------- K0: fp32 -> int8 (hi, lo) quantization ----------------
__global__ void quant_kernel(const float* __restrict__ src,
                             int8_t* __restrict__ hi, int8_t* __restrict__ lo, float S) {
    size_t i = (size_t)blockIdx.x * blockDim.x + threadIdx.x;
    float4 f = ((const float4*)src)[i];
    float v[4] = {f.x, f.y, f.z, f.w};
    char h[4], l[4];
#pragma unroll
    for (int j = 0; j < 4; j++) {
        int q = __float2int_rn(fminf(fmaxf(v[j] * S, -32640.f), 32639.f));
        int qh = (q + 128) >> 8;           // qh in [-127,127]
        int ql = q - (qh << 8);            // ql in [-128,127], exact
        h[j] = (char)qh; l[j] = (char)ql;
    }
    ((char4*)hi)[i] = make_char4(h[0], h[1], h[2], h[3]);
    ((char4*)lo)[i] = make_char4(l[0], l[1], l[2], l[3]);
}

// ---------------- K1: exact int16-via-int8 GEMM  u = x @ W^T + bias ----------
#define BM 128
#define BN 64
#define BK 32
#define STAGES 4
#define NSTG (DIN / BK)            // 32
#define PITCH 48                   // 32 B data + 16 B pad
#define T_A (BM * PITCH)           // 6144
#define T_B (BN * PITCH)           // 3072
#define STG_BYTES (2 * T_A + 2 * T_B)     // 18432: AH | AL | BH | BL
#define SMEM_TOTAL (STAGES * STG_BYTES)   // 73728

__global__ void __launch_bounds__(512, 1)
gemm_kernel(const float* __restrict__ bias) {
    extern __shared__ __align__(128) char smem[];
    uint32_t sb = smem_u32(smem);
    const int tid  = threadIdx.x;
    const int wid  = tid >> 5;
    const int lane = tid & 31;

    // rasterization: 16 m-tiles per group; within group m varies fastest -> B tile L2-hot
    const int NT = NTOT / BN;      // 192
    const int GM = 16;
    int id = blockIdx.x;
    int group = id / (GM * NT), rem = id % (GM * NT);
    const int m0 = (group * GM + (rem % GM)) * BM;
    const int n0 = (rem / GM) * BN;

    // 16 warps: 4 m x 4 n; warp tile 32 x 16
    const int wr = wid & 3;
    const int wc = wid >> 2;

    // cp.async mapping: each thread 1 A chunk (mat = tid&1); threads<256 also 1 B chunk
    const int amat = tid & 1;
    const int ar = tid >> 2, ach = (tid >> 1) & 1;
    const uint32_t a_soff = (uint32_t)(amat * T_A + ar * PITCH + ach * 16);
    const int8_t* a_src = (amat ? g_xl8 : g_xh8) + (size_t)(m0 + ar) * DIN + ach * 16;

    const int bmat = tid & 1;
    const int br = tid >> 2, bch = (tid >> 1) & 1;
    const uint32_t b_soff = (uint32_t)(2 * T_A + bmat * T_B + br * PITCH + bch * 16);
    const int8_t* b_src = (bmat ? g_wl8 : g_wh8) + (size_t)(n0 + br) * DIN + bch * 16;
    const bool do_b = (tid < 256);

    auto load_stage = [&](int ks) {
        uint32_t st = sb + (ks & 3) * STG_BYTES;
        int koff = ks * BK;
        cp_async16(st + a_soff, a_src + koff);
        if (do_b) cp_async16(st + b_soff, b_src + koff);
        CP_COMMIT();
    };

    int c1[2][2][4], c2[2][2][4], c3[2][2][4];
#pragma unroll
    for (int i = 0; i < 2; i++)
#pragma unroll
        for (int j = 0; j < 2; j++)
#pragma unroll
            for (int k = 0; k < 4; k++) { c1[i][j][k] = 0; c2[i][j][k] = 0; c3[i][j][k] = 0; }

    load_stage(0); load_stage(1); load_stage(2);

    const uint32_t a_lane = (uint32_t)(((lane & 7) + ((lane >> 3) & 1) * 8) * PITCH
                                       + (lane >> 4) * 16);
    const uint32_t b_lane = (uint32_t)(((lane & 7) + (lane >> 4) * 8) * PITCH
                                       + ((lane >> 3) & 1) * 16);

    for (int ks = 0; ks < NSTG; ks++) {
        if (ks < NSTG - 2)       { CP_WAIT(2); }
        else if (ks == NSTG - 2) { CP_WAIT(1); }
        else                     { CP_WAIT(0); }
        __syncthreads();
        if (ks + 3 < NSTG) load_stage(ks + 3);

        uint32_t st = sb + (ks & 3) * STG_BYTES;
        uint32_t ah_base = st + wr * 32 * PITCH + a_lane;
        uint32_t al_base = ah_base + T_A;
        uint32_t bh_base = st + 2 * T_A + wc * 16 * PITCH + b_lane;
        uint32_t bl_base = bh_base + T_B;

        uint32_t ah[2][4], al[2][4], bh[4], bl[4];
#pragma unroll
        for (int mt = 0; mt < 2; mt++) {
            ldsm_x4(ah_base + mt * 16 * PITCH, ah[mt][0], ah[mt][1], ah[mt][2], ah[mt][3]);
            ldsm_x4(al_base + mt * 16 * PITCH, al[mt][0], al[mt][1], al[mt][2], al[mt][3]);
        }
        ldsm_x4(bh_base, bh[0], bh[1], bh[2], bh[3]);
        ldsm_x4(bl_base, bl[0], bl[1], bl[2], bl[3]);

        // sweep 1: hi*hi -> c1, hi*lo -> c2
#pragma unroll
        for (int mt = 0; mt < 2; mt++)
#pragma unroll
            for (int p = 0; p < 2; p++) {
                mma_s8(c1[mt][p], ah[mt], bh + 2 * p);
                mma_s8(c2[mt][p], ah[mt], bl + 2 * p);
            }
        // sweep 2: lo*hi -> c2, lo*lo -> c3 (c2 retouch spaced by 8 mmas)
#pragma unroll
        for (int mt = 0; mt < 2; mt++)
#pragma unroll
            for (int p = 0; p < 2; p++) {
                mma_s8(c2[mt][p], al[mt], bh + 2 * p);
                mma_s8(c3[mt][p], al[mt], bl + 2 * p);
            }
        __syncthreads();
    }

    // epilogue: u = (c1*65536 + c2*256 + c3)/(SX*SW) + bias  (exact combine in fp32)
    const float fin = 1.f / (SX * SW);
    const int rbase = m0 + wr * 32 + (lane >> 2);
    const int cbase = n0 + wc * 16 + (lane & 3) * 2;
#pragma unroll
    for (int nt = 0; nt < 2; nt++) {
        int col = cbase + nt * 8;
        float2 bv = *(const float2*)(bias + col);
#pragma unroll
        for (int mt = 0; mt < 2; mt++) {
            int r0 = rbase + mt * 16;
            float t0 = fmaf((float)c1[mt][nt][0], 65536.f, fmaf((float)c2[mt][nt][0], 256.f, (float)c3[mt][nt][0]));
            float t1 = fmaf((float)c1[mt][nt][1], 65536.f, fmaf((float)c2[mt][nt][1], 256.f, (float)c3[mt][nt][1]));
            float t2 = fmaf((float)c1[mt][nt][2], 65536.f, fmaf((float)c2[mt][nt][2], 256.f, (float)c3[mt][nt][2]));
            float t3 = fmaf((float)c1[mt][nt][3], 65536.f, fmaf((float)c2[mt][nt][3], 256.f, (float)c3[mt][nt][3]));
            float* p0 = g_u + (size_t)r0 * NTOT + col;
            float* p1 = g_u + (size_t)(r0 + 8) * NTOT + col;
            *(float2*)p0 = make_float2(fmaf(t0, fin, bv.x), fmaf(t1, fin, bv.y));
            *(float2*)p1 = make_float2(fmaf(t2, fin, bv.x), fmaf(t3, fin, bv.y));
        }
    }
}

// ---------------- K2: per-row routing + entropy ----------------
__device__ __forceinline__ float bsum(float v, float* s8, int wid, int lid) {
#pragma unroll
    for (int o = 16; o > 0; o >>= 1) v += __shfl_down_sync(0xffffffffu, v, o);
    __syncthreads();
    if (lid == 0) s8[wid] = v;
    __syncthreads();
    float r = 0.f;
#pragma unroll
    for (int w = 0; w < 8; w++) r += s8[w];
    return r;
}
__device__ __forceinline__ float bmax(float v, float* s8, int wid, int lid) {
#pragma unroll
    for (int o = 16; o > 0; o >>= 1) v = fmaxf(v, __shfl_down_sync(0xffffffffu, v, o));
    __syncthreads();
    if (lid == 0) s8[wid] = v;
    __syncthreads();
    float r = s8[0];
#pragma unroll
    for (int w = 1; w < 8; w++) r = fmaxf(r, s8[w]);
    return r;
}

__global__ void __launch_bounds__(256) routing_kernel(float* __restrict__ out) {
    __shared__ float s_red[8 * CCAP];
    __shared__ float s_s8[8];
    int b = blockIdx.x, tid = threadIdx.x;
    int wid = tid >> 5, lid = tid & 31;

    const float* up = g_u + (size_t)b * NTOT + tid * 4;
    float u[CCAP][4];
#pragma unroll
    for (int cc = 0; cc < CCAP; cc++) {
        float4 f = *(const float4*)(up + cc * DOUT);
        u[cc][0] = f.x; u[cc][1] = f.y; u[cc][2] = f.z; u[cc][3] = f.w;
    }

    float blog[CCAP];
#pragma unroll
    for (int cc = 0; cc < CCAP; cc++) blog[cc] = 0.f;

    float s[4] = {0.f, 0.f, 0.f, 0.f}, scale = 0.f;
#pragma unroll 1
    for (int it = 0; it < 3; it++) {
        float mx = blog[0];
#pragma unroll
        for (int cc = 1; cc < CCAP; cc++) mx = fmaxf(mx, blog[cc]);
        float cw[CCAP], csum = 0.f;
#pragma unroll
        for (int cc = 0; cc < CCAP; cc++) { cw[cc] = expf(blog[cc] - mx); csum += cw[cc]; }
        float inv = 1.f / csum;
#pragma unroll
        for (int j = 0; j < 4; j++) {
            float a = 0.f;
#pragma unroll
            for (int cc = 0; cc < CCAP; cc++) a += cw[cc] * u[cc][j];
            s[j] = a * inv;
        }
        float n2 = bsum(s[0]*s[0] + s[1]*s[1] + s[2]*s[2] + s[3]*s[3], s_s8, wid, lid);
        float nrm = sqrtf(n2);
        scale = n2 / ((1.f + n2) * (nrm + 1e-8f));
        if (it < 2) {
            float dp[CCAP];
#pragma unroll
            for (int cc = 0; cc < CCAP; cc++) {
                float a = u[cc][0]*s[0] + u[cc][1]*s[1] + u[cc][2]*s[2] + u[cc][3]*s[3];
#pragma unroll
                for (int o = 16; o > 0; o >>= 1) a += __shfl_down_sync(0xffffffffu, a, o);
                dp[cc] = a;
            }
            __syncthreads();
            if (lid == 0)
#pragma unroll
                for (int cc = 0; cc < CCAP; cc++) s_red[wid * CCAP + cc] = dp[cc];
            __syncthreads();
#pragma unroll
            for (int cc = 0; cc < CCAP; cc++) {
                float d = 0.f;
#pragma unroll
                for (int w = 0; w < 8; w++) d += s_red[w * CCAP + cc];
                blog[cc] += scale * d;
            }
        }
    }

    float4 v4 = make_float4(scale * s[0], scale * s[1], scale * s[2], scale * s[3]);
    size_t obase = ((size_t)b * AREP) * DOUT + tid * 4;
#pragma unroll
    for (int a = 0; a < AREP; a++) *(float4*)(out + obase + (size_t)a * DOUT) = v4;

    float smx = bmax(fmaxf(fmaxf(s[0], s[1]), fmaxf(s[2], s[3])), s_s8, wid, lid);
    float e[4], zp = 0.f;
#pragma unroll
    for (int j = 0; j < 4; j++) { e[j] = expf(s[j] - smx); zp += e[j]; }
    float Z = bsum(zp, s_s8, wid, lid) + 1e-10f;
    float ep = 0.f;
#pragma unroll
    for (int j = 0; j < 4; j++) { float p = e[j] / Z; ep -= p * logf(p + 1e-10f); }
    float ent = bsum(ep, s_s8, wid, lid);
    if (tid == 0) g_ent[b] = fminf(fmaxf(ent, 0.f), 10.f);
}

// ---------------- K3: entropy loss scalar ----------------
__global__ void loss_kernel(float* __restrict__ dst) {
    __shared__ float s8[8];
    int tid = threadIdx.x, wid = tid >> 5, lid = tid & 31;
    float a = 0.f;
    for (int i = tid; i < BB; i += 256) a += g_ent[i];
#pragma unroll
    for (int o = 16; o > 0; o >>= 1) a += __shfl_down_sync(0xffffffffu, a, o);
    if (lid == 0) s8[wid] = a;
    __syncthreads();
    if (tid == 0) {
        float t = 0.f;
#pragma unroll
        for (int w = 0; w < 8; w++) t += s8[w];
        float mean = t / (float)BB;
        dst[0] = -(1.f / (1.f + expf(-mean))) * 0.4f;
    }
}

// ---------------- launch ----------------
extern "C" void kernel_launch(void* const* d_in, const int* in_sizes, int n_in,
                              void* d_out, int out_size) {
    const float* x    = (const float*)d_in[0];
    const float* W    = (const float*)d_in[1];
    const float* bias = (const float*)d_in[2];
    float* out = (float*)d_out;

    cudaFuncSetAttribute(gemm_kernel, cudaFuncAttributeMaxDynamicSharedMemorySize, SMEM_TOTAL);

    int8_t *xh, *xl, *wh, *wl;
    cudaGetSymbolAddress((void**)&xh, g_xh8);
    cudaGetSymbolAddress((void**)&xl, g_xl8);
    cudaGetSymbolAddress((void**)&wh, g_wh8);
    cudaGetSymbolAddress((void**)&wl, g_wl8);

    quant_kernel<<<(BB * DIN / 4) / 256, 256>>>(x, xh, xl, SX);
    quant_kernel<<<((size_t)NTOT * DIN / 4) / 256, 256>>>(W, wh, wl, SW);
    gemm_kernel<<<(BB / BM) * (NTOT / BN), 512, SMEM_TOTAL>>>(bias);
    routing_kernel<<<BB, 256>>>(out);
    loss_kernel<<<1, 256>>>(out + (size_t)out_size - 1);
}

// round 11
// speedup vs baseline: 2.3870x; 2.2374x over previous
#include <cuda_runtime.h>
#include <cuda_fp16.h>
#include <cuda_fp8.h>
#include <cstdint>
#include <cstddef>

#define BB    8192
#define DIN   1024
#define CCAP  12
#define DOUT  1024
#define NTOT  12288
#define AREP  8

// ---------------- device scratch (static; no allocation) ----------------
__device__ __half  g_xh[(size_t)BB * DIN];       // fp16(x)
__device__ uint8_t g_xl8[(size_t)BB * DIN];      // e4m3((x - fp16(x)) * 512)
__device__ uint8_t g_x8 [(size_t)BB * DIN];      // e4m3(x)
__device__ __half  g_wh[(size_t)NTOT * DIN];     // fp16(W)
__device__ uint8_t g_w8 [(size_t)NTOT * DIN];    // e4m3(W * 16)
__device__ uint8_t g_wl8[(size_t)NTOT * DIN];    // e4m3((W - fp16(W)) * 8192)
__device__ float   g_u [(size_t)BB * NTOT];      // 384 MB
__device__ float   g_ent[BB];

// ---------------- PTX helpers ----------------
__device__ __forceinline__ uint32_t smem_u32(const void* p) {
    uint32_t a;
    asm("{ .reg .u64 t; cvta.to.shared.u64 t, %1; cvt.u32.u64 %0, t; }" : "=r"(a) : "l"(p));
    return a;
}
__device__ __forceinline__ void cp_async16(uint32_t sdst, const void* gsrc) {
    asm volatile("cp.async.cg.shared.global [%0], [%1], 16;" :: "r"(sdst), "l"(gsrc) : "memory");
}
#define CP_COMMIT() asm volatile("cp.async.commit_group;" ::: "memory")
#define CP_WAIT(N)  asm volatile("cp.async.wait_group %0;" :: "n"(N) : "memory")

__device__ __forceinline__ void ldsm_x4(uint32_t addr, uint32_t& r0, uint32_t& r1,
                                        uint32_t& r2, uint32_t& r3) {
    asm volatile("ldmatrix.sync.aligned.m8n8.x4.shared.b16 {%0,%1,%2,%3}, [%4];"
                 : "=r"(r0), "=r"(r1), "=r"(r2), "=r"(r3) : "r"(addr));
}
__device__ __forceinline__ void mma_f16(float* c, const uint32_t* a, const uint32_t* b) {
    asm volatile(
        "mma.sync.aligned.m16n8k16.row.col.f32.f16.f16.f32 "
        "{%0,%1,%2,%3},{%4,%5,%6,%7},{%8,%9},{%0,%1,%2,%3};"
        : "+f"(c[0]), "+f"(c[1]), "+f"(c[2]), "+f"(c[3])
        : "r"(a[0]), "r"(a[1]), "r"(a[2]), "r"(a[3]), "r"(b[0]), "r"(b[1]));
}
__device__ __forceinline__ void mma_f8(float* c, const uint32_t* a, const uint32_t* b) {
    asm volatile(
        "mma.sync.aligned.m16n8k32.row.col.f32.e4m3.e4m3.f32 "
        "{%0,%1,%2,%3},{%4,%5,%6,%7},{%8,%9},{%0,%1,%2,%3};"
        : "+f"(c[0]), "+f"(c[1]), "+f"(c[2]), "+f"(c[3])
        : "r"(a[0]), "r"(a[1]), "r"(a[2]), "r"(a[3]), "r"(b[0]), "r"(b[1]));
}

// ---------------- K0: input preparation ----------------
__device__ __forceinline__ uint8_t to_e4m3(float v) {
    return (uint8_t)__nv_cvt_float_to_fp8(v, __NV_SATFINITE, __NV_E4M3);
}
__global__ void prep_x(const float* __restrict__ src) {
    size_t i = (size_t)blockIdx.x * blockDim.x + threadIdx.x;
    float4 f = ((const float4*)src)[i];
    float v[4] = {f.x, f.y, f.z, f.w};
    __half h[4]; uint8_t l8[4], v8[4];
#pragma unroll
    for (int j = 0; j < 4; j++) {
        h[j] = __float2half_rn(v[j]);
        float lo = v[j] - __half2float(h[j]);
        l8[j] = to_e4m3(lo * 512.f);
        v8[j] = to_e4m3(v[j]);
    }
    ((__half2*)g_xh)[2*i]   = __halves2half2(h[0], h[1]);
    ((__half2*)g_xh)[2*i+1] = __halves2half2(h[2], h[3]);
    ((uchar4*)g_xl8)[i] = make_uchar4(l8[0], l8[1], l8[2], l8[3]);
    ((uchar4*)g_x8)[i]  = make_uchar4(v8[0], v8[1], v8[2], v8[3]);
}
__global__ void prep_w(const float* __restrict__ src) {
    size_t i = (size_t)blockIdx.x * blockDim.x + threadIdx.x;
    float4 f = ((const float4*)src)[i];
    float v[4] = {f.x, f.y, f.z, f.w};
    __half h[4]; uint8_t w8[4], l8[4];
#pragma unroll
    for (int j = 0; j < 4; j++) {
        h[j] = __float2half_rn(v[j]);
        float lo = v[j] - __half2float(h[j]);
        w8[j] = to_e4m3(v[j] * 16.f);
        l8[j] = to_e4m3(lo * 8192.f);
    }
    ((__half2*)g_wh)[2*i]   = __halves2half2(h[0], h[1]);
    ((__half2*)g_wh)[2*i+1] = __halves2half2(h[2], h[3]);
    ((uchar4*)g_w8)[i]  = make_uchar4(w8[0], w8[1], w8[2], w8[3]);
    ((uchar4*)g_wl8)[i] = make_uchar4(l8[0], l8[1], l8[2], l8[3]);
}

// ---------------- K1: fused fp16 + fp8 GEMM  u = x @ W^T + bias ----------
#define BM 128
#define BN 128
#define BK 32
#define STAGES 4
#define NSTG (DIN / BK)            // 32
#define P16 80                     // fp16 row pitch: 64 B data + 16 pad
#define P8  48                     // fp8 row pitch: 32 B data + 16 pad
#define T16 (128 * P16)            // 10240
#define T8  (128 * P8)             // 6144
#define O_B16  T16                 // 10240
#define O_A8A  (2 * T16)           // 20480  e4m3(x_lo*512)
#define O_A8B  (2 * T16 + T8)      // 26624  e4m3(x)
#define O_B8A  (2 * T16 + 2 * T8)  // 32768  e4m3(W*16)
#define O_B8B  (2 * T16 + 3 * T8)  // 38912  e4m3(W_lo*8192)
#define STG_BYTES (2 * T16 + 4 * T8)      // 45056
#define SMEM_TOTAL (STAGES * STG_BYTES)   // 180224

__global__ void __launch_bounds__(256, 1)
gemm_kernel(const float* __restrict__ bias) {
    extern __shared__ __align__(128) char smem[];
    uint32_t sb = smem_u32(smem);
    const int tid  = threadIdx.x;
    const int wid  = tid >> 5;
    const int lane = tid & 31;

    // rasterization: 32 m-tiles per group, m fastest (A group stays L2-hot across n sweep)
    const int NT = NTOT / BN;      // 96
    const int GM = 32;
    int id = blockIdx.x;
    int group = id / (GM * NT), rem = id % (GM * NT);
    const int m0 = (group * GM + (rem % GM)) * BM;
    const int n0 = (rem / GM) * BN;

    // 8 warps: 2 m x 4 n; warp tile 64 x 32
    const int wr = wid & 1;
    const int wc = wid >> 1;

    // cp.async mapping
    const int r16 = tid >> 2, c16c = tid & 3;                 // fp16: 4 chunks/row, 2 iters
    const uint32_t s16 = (uint32_t)(r16 * P16 + c16c * 16);
    const int r8 = tid >> 1, c8c = tid & 1;                   // fp8: 2 chunks/row, 1 iter
    const uint32_t s8o = (uint32_t)(r8 * P8 + c8c * 16);

    auto load_stage = [&](int ks) {
        uint32_t st = sb + (ks & 3) * STG_BYTES;
        int k0 = ks * BK;   // element offset
        // fp16 A and B: 128 rows x 4 chunks = 512 each; 256 threads x 2
#pragma unroll
        for (int i = 0; i < 2; i++) {
            int idx = i * 256 + tid, rr = idx >> 2, cc = idx & 3;
            uint32_t so = (uint32_t)(rr * P16 + cc * 16);
            cp_async16(st + so,         g_xh + (size_t)(m0 + rr) * DIN + k0 + cc * 8);
            cp_async16(st + O_B16 + so, g_wh + (size_t)(n0 + rr) * DIN + k0 + cc * 8);
        }
        // fp8: 4 matrices, 128 rows x 2 chunks = 256 each; 1 per thread per matrix
        cp_async16(st + O_A8A + s8o, g_xl8 + (size_t)(m0 + r8) * DIN + k0 + c8c * 16);
        cp_async16(st + O_A8B + s8o, g_x8  + (size_t)(m0 + r8) * DIN + k0 + c8c * 16);
        cp_async16(st + O_B8A + s8o, g_w8  + (size_t)(n0 + r8) * DIN + k0 + c8c * 16);
        cp_async16(st + O_B8B + s8o, g_wl8 + (size_t)(n0 + r8) * DIN + k0 + c8c * 16);
        CP_COMMIT();
    };

    float c[4][4][4], d[4][4][4];
#pragma unroll
    for (int i = 0; i < 4; i++)
#pragma unroll
        for (int j = 0; j < 4; j++)
#pragma unroll
            for (int k = 0; k < 4; k++) { c[i][j][k] = 0.f; d[i][j][k] = 0.f; }

    load_stage(0); load_stage(1); load_stage(2);

    // fp16 lane addressing (R4-validated)
    const uint32_t a16_lane = (uint32_t)((lane & 15) * P16 + (lane >> 4) * 16);
    const uint32_t b16_lane = (uint32_t)(((lane & 7) + ((lane >> 4) & 1) * 8) * P16
                                         + ((lane >> 3) & 1) * 16);
    // fp8 lane addressing (R7-validated, same as s8 k32)
    const uint32_t a8_lane = (uint32_t)(((lane & 7) + ((lane >> 3) & 1) * 8) * P8
                                        + (lane >> 4) * 16);
    const uint32_t b8_lane = (uint32_t)(((lane & 7) + ((lane >> 4) & 1) * 8) * P8
                                        + ((lane >> 3) & 1) * 16);

    for (int ks = 0; ks < NSTG; ks++) {
        if (ks < NSTG - 2)       { CP_WAIT(2); }
        else if (ks == NSTG - 2) { CP_WAIT(1); }
        else                     { CP_WAIT(0); }
        __syncthreads();
        if (ks + 3 < NSTG) load_stage(ks + 3);

        uint32_t st = sb + (ks & 3) * STG_BYTES;

        // ---- fp16 main term: 2 k16 steps ----
        {
            uint32_t aw = st + wr * 64 * P16 + a16_lane;
            uint32_t bw = st + O_B16 + wc * 32 * P16 + b16_lane;
#pragma unroll
            for (int kk = 0; kk < 2; kk++) {
                uint32_t ko = kk * 32;   // 16 halfs = 32 B
                uint32_t a[4][4], b[4][2];
#pragma unroll
                for (int mt = 0; mt < 4; mt++)
                    ldsm_x4(aw + mt * 16 * P16 + ko, a[mt][0], a[mt][1], a[mt][2], a[mt][3]);
#pragma unroll
                for (int q = 0; q < 2; q++) {
                    uint32_t r0, r1, r2, r3;
                    ldsm_x4(bw + q * 16 * P16 + ko, r0, r1, r2, r3);
                    b[q*2][0] = r0; b[q*2][1] = r1; b[q*2+1][0] = r2; b[q*2+1][1] = r3;
                }
#pragma unroll
                for (int mt = 0; mt < 4; mt++)
#pragma unroll
                    for (int nt = 0; nt < 4; nt++)
                        mma_f16(c[mt][nt], a[mt], b[nt]);
            }
        }

        // ---- fp8 corrections: 1 k32 step, 2 terms, common scale 8192 ----
        {
            uint32_t awa = st + O_A8A + wr * 64 * P8 + a8_lane;
            uint32_t awb = st + O_A8B + wr * 64 * P8 + a8_lane;
            uint32_t bwa = st + O_B8A + wc * 32 * P8 + b8_lane;
            uint32_t bwb = st + O_B8B + wc * 32 * P8 + b8_lane;
            uint32_t ba[4][2], bb[4][2];
#pragma unroll
            for (int q = 0; q < 2; q++) {
                uint32_t r0, r1, r2, r3;
                ldsm_x4(bwa + q * 16 * P8, r0, r1, r2, r3);
                ba[q*2][0] = r0; ba[q*2][1] = r1; ba[q*2+1][0] = r2; ba[q*2+1][1] = r3;
                ldsm_x4(bwb + q * 16 * P8, r0, r1, r2, r3);
                bb[q*2][0] = r0; bb[q*2][1] = r1; bb[q*2+1][0] = r2; bb[q*2+1][1] = r3;
            }
#pragma unroll
            for (int mt = 0; mt < 4; mt++) {
                uint32_t aa[4], ab[4];
                ldsm_x4(awa + mt * 16 * P8, aa[0], aa[1], aa[2], aa[3]);
                ldsm_x4(awb + mt * 16 * P8, ab[0], ab[1], ab[2], ab[3]);
#pragma unroll
                for (int nt = 0; nt < 4; nt++) {
                    mma_f8(d[mt][nt], aa, ba[nt]);   // x_lo*512 · W*16
                    mma_f8(d[mt][nt], ab, bb[nt]);   // x · W_lo*8192
                }
            }
        }
        __syncthreads();
    }

    // epilogue: u = c + d/8192 + bias
    const float fin = 1.f / 8192.f;
    const int rbase = m0 + wr * 64 + (lane >> 2);
    const int cbase = n0 + wc * 32 + (lane & 3) * 2;
#pragma unroll
    for (int nt = 0; nt < 4; nt++) {
        int col = cbase + nt * 8;
        float2 bv = *(const float2*)(bias + col);
#pragma unroll
        for (int mt = 0; mt < 4; mt++) {
            int r0 = rbase + mt * 16;
            float* p0 = g_u + (size_t)r0 * NTOT + col;
            float* p1 = g_u + (size_t)(r0 + 8) * NTOT + col;
            *(float2*)p0 = make_float2(fmaf(d[mt][nt][0], fin, c[mt][nt][0]) + bv.x,
                                       fmaf(d[mt][nt][1], fin, c[mt][nt][1]) + bv.y);
            *(float2*)p1 = make_float2(fmaf(d[mt][nt][2], fin, c[mt][nt][2]) + bv.x,
                                       fmaf(d[mt][nt][3], fin, c[mt][nt][3]) + bv.y);
        }
    }
}

// ---------------- K2: per-row routing + entropy ----------------
__device__ __forceinline__ float bsum(float v, float* s8, int wid, int lid) {
#pragma unroll
    for (int o = 16; o > 0; o >>= 1) v += __shfl_down_sync(0xffffffffu, v, o);
    __syncthreads();
    if (lid == 0) s8[wid] = v;
    __syncthreads();
    float r = 0.f;
#pragma unroll
    for (int w = 0; w < 8; w++) r += s8[w];
    return r;
}
__device__ __forceinline__ float bmax(float v, float* s8, int wid, int lid) {
#pragma unroll
    for (int o = 16; o > 0; o >>= 1) v = fmaxf(v, __shfl_down_sync(0xffffffffu, v, o));
    __syncthreads();
    if (lid == 0) s8[wid] = v;
    __syncthreads();
    float r = s8[0];
#pragma unroll
    for (int w = 1; w < 8; w++) r = fmaxf(r, s8[w]);
    return r;
}

__global__ void __launch_bounds__(256) routing_kernel(float* __restrict__ out) {
    __shared__ float s_red[8 * CCAP];
    __shared__ float s_s8[8];
    int b = blockIdx.x, tid = threadIdx.x;
    int wid = tid >> 5, lid = tid & 31;

    const float* up = g_u + (size_t)b * NTOT + tid * 4;
    float u[CCAP][4];
#pragma unroll
    for (int cc = 0; cc < CCAP; cc++) {
        float4 f = *(const float4*)(up + cc * DOUT);
        u[cc][0] = f.x; u[cc][1] = f.y; u[cc][2] = f.z; u[cc][3] = f.w;
    }

    float blog[CCAP];
#pragma unroll
    for (int cc = 0; cc < CCAP; cc++) blog[cc] = 0.f;

    float s[4] = {0.f, 0.f, 0.f, 0.f}, scale = 0.f;
#pragma unroll 1
    for (int it = 0; it < 3; it++) {
        float mx = blog[0];
#pragma unroll
        for (int cc = 1; cc < CCAP; cc++) mx = fmaxf(mx, blog[cc]);
        float cw[CCAP], csum = 0.f;
#pragma unroll
        for (int cc = 0; cc < CCAP; cc++) { cw[cc] = expf(blog[cc] - mx); csum += cw[cc]; }
        float inv = 1.f / csum;
#pragma unroll
        for (int j = 0; j < 4; j++) {
            float a = 0.f;
#pragma unroll
            for (int cc = 0; cc < CCAP; cc++) a += cw[cc] * u[cc][j];
            s[j] = a * inv;
        }
        float n2 = bsum(s[0]*s[0] + s[1]*s[1] + s[2]*s[2] + s[3]*s[3], s_s8, wid, lid);
        float nrm = sqrtf(n2);
        scale = n2 / ((1.f + n2) * (nrm + 1e-8f));
        if (it < 2) {
            float dp[CCAP];
#pragma unroll
            for (int cc = 0; cc < CCAP; cc++) {
                float a = u[cc][0]*s[0] + u[cc][1]*s[1] + u[cc][2]*s[2] + u[cc][3]*s[3];
#pragma unroll
                for (int o = 16; o > 0; o >>= 1) a += __shfl_down_sync(0xffffffffu, a, o);
                dp[cc] = a;
            }
            __syncthreads();
            if (lid == 0)
#pragma unroll
                for (int cc = 0; cc < CCAP; cc++) s_red[wid * CCAP + cc] = dp[cc];
            __syncthreads();
#pragma unroll
            for (int cc = 0; cc < CCAP; cc++) {
                float dd = 0.f;
#pragma unroll
                for (int w = 0; w < 8; w++) dd += s_red[w * CCAP + cc];
                blog[cc] += scale * dd;
            }
        }
    }

    float4 v4 = make_float4(scale * s[0], scale * s[1], scale * s[2], scale * s[3]);
    size_t obase = ((size_t)b * AREP) * DOUT + tid * 4;
#pragma unroll
    for (int a = 0; a < AREP; a++) *(float4*)(out + obase + (size_t)a * DOUT) = v4;

    float smx = bmax(fmaxf(fmaxf(s[0], s[1]), fmaxf(s[2], s[3])), s_s8, wid, lid);
    float e[4], zp = 0.f;
#pragma unroll
    for (int j = 0; j < 4; j++) { e[j] = expf(s[j] - smx); zp += e[j]; }
    float Z = bsum(zp, s_s8, wid, lid) + 1e-10f;
    float ep = 0.f;
#pragma unroll
    for (int j = 0; j < 4; j++) { float p = e[j] / Z; ep -= p * logf(p + 1e-10f); }
    float ent = bsum(ep, s_s8, wid, lid);
    if (tid == 0) g_ent[b] = fminf(fmaxf(ent, 0.f), 10.f);
}

// ---------------- K3: entropy loss scalar ----------------
__global__ void loss_kernel(float* __restrict__ dst) {
    __shared__ float s8[8];
    int tid = threadIdx.x, wid = tid >> 5, lid = tid & 31;
    float a = 0.f;
    for (int i = tid; i < BB; i += 256) a += g_ent[i];
#pragma unroll
    for (int o = 16; o > 0; o >>= 1) a += __shfl_down_sync(0xffffffffu, a, o);
    if (lid == 0) s8[wid] = a;
    __syncthreads();
    if (tid == 0) {
        float t = 0.f;
#pragma unroll
        for (int w = 0; w < 8; w++) t += s8[w];
        float mean = t / (float)BB;
        dst[0] = -(1.f / (1.f + expf(-mean))) * 0.4f;
    }
}

// ---------------- launch ----------------
extern "C" void kernel_launch(void* const* d_in, const int* in_sizes, int n_in,
                              void* d_out, int out_size) {
    const float* x    = (const float*)d_in[0];
    const float* W    = (const float*)d_in[1];
    const float* bias = (const float*)d_in[2];
    float* out = (float*)d_out;

    cudaFuncSetAttribute(gemm_kernel, cudaFuncAttributeMaxDynamicSharedMemorySize, SMEM_TOTAL);

    prep_x<<<(BB * DIN / 4) / 256, 256>>>(x);
    prep_w<<<((size_t)NTOT * DIN / 4) / 256, 256>>>(W);
    gemm_kernel<<<(BB / BM) * (NTOT / BN), 256, SMEM_TOTAL>>>(bias);
    routing_kernel<<<BB, 256>>>(out);
    loss_kernel<<<1, 256>>>(out + (size_t)out_size - 1);
}